// round 12
// baseline (speedup 1.0000x reference)
#include <cuda_runtime.h>
#include <cuda_bf16.h>
#include <cstdint>

// Problem constants (fixed: N=131072, C=1024, D=128)
#define NROWS 131072
#define CROWS 1024
#define DDIM  128

#define BM 128
#define BN 128
// smem: A tile 32KB + B tile 32KB; epilogue staging reuses the same 64KB
// (8 warps x 8KB warp-private regions).
#define SMEM_NEED 65536

// ---------------------------------------------------------------------------
// Device scratch (no cudaMalloc allowed)
// ---------------------------------------------------------------------------
__device__ float g_xsq[NROWS];
__device__ float g_wsq[CROWS];
__device__ __nv_bfloat16 g_xb[(size_t)NROWS * DDIM];  // bf16(x)
__device__ __nv_bfloat16 g_wb[(size_t)CROWS * DDIM];

// ---------------------------------------------------------------------------
// PTX helpers — base-target-safe only (NO tcgen05: harness targets plain sm_103)
// ---------------------------------------------------------------------------
__device__ __forceinline__ uint32_t smem_u32(const void* p) {
    uint32_t a;
    asm("{ .reg .u64 t; cvta.to.shared.u64 t, %1; cvt.u32.u64 %0, t; }"
        : "=r"(a) : "l"(p));
    return a;
}

__device__ __forceinline__ void cp_async16(uint32_t dst, const void* src) {
    asm volatile("cp.async.cg.shared.global [%0], [%1], 16;"
                 :: "r"(dst), "l"(src));
}
#define CP_COMMIT()  asm volatile("cp.async.commit_group;" ::: "memory")
#define CP_WAIT0()   asm volatile("cp.async.wait_group 0;" ::: "memory")

__device__ __forceinline__ void ldsm_x4(uint32_t& r0, uint32_t& r1,
                                        uint32_t& r2, uint32_t& r3, uint32_t a) {
    asm volatile("ldmatrix.sync.aligned.m8n8.x4.shared.b16 {%0,%1,%2,%3}, [%4];"
                 : "=r"(r0), "=r"(r1), "=r"(r2), "=r"(r3) : "r"(a));
}

__device__ __forceinline__ void mma16816(float* c, const uint32_t* a,
                                         const uint32_t* b) {
    asm volatile(
        "mma.sync.aligned.m16n8k16.row.col.f32.bf16.bf16.f32 "
        "{%0,%1,%2,%3}, {%4,%5,%6,%7}, {%8,%9}, {%0,%1,%2,%3};"
        : "+f"(c[0]), "+f"(c[1]), "+f"(c[2]), "+f"(c[3])
        : "r"(a[0]), "r"(a[1]), "r"(a[2]), "r"(a[3]), "r"(b[0]), "r"(b[1]));
}

__device__ __forceinline__ void stcs_f4(float* p, float4 v) {
    asm volatile("st.global.cs.v4.f32 [%0], {%1,%2,%3,%4};"
                 :: "l"(p), "f"(v.x), "f"(v.y), "f"(v.z), "f"(v.w) : "memory");
}

// 256B-pitch row swizzle for bf16 tiles: 16B unit u (0..15) XOR (row & 7).
__device__ __forceinline__ uint32_t tile_off(int row, int u) {
    return (uint32_t)(row * 256 + ((u ^ (row & 7)) << 4));
}

// Epilogue staging swizzle (fp32, 128B rows of 16 8B units):
// rotate units by 2*(row&7) -> STS.64 2-way (min), LDS.128 4-way (min),
// and u,u+1 stay adjacent so 16B reads work.
__device__ __forceinline__ uint32_t stage_off(int row, int u) {
    return (uint32_t)(row * 128 + (((u + 2 * (row & 7)) & 15) << 3));
}

// ---------------------------------------------------------------------------
// Kernel 1: fp32 -> bf16 conversion + exact fp32 row norms. One warp per row.
// ---------------------------------------------------------------------------
__global__ __launch_bounds__(256)
void convert_kernel(const float* __restrict__ x, const float* __restrict__ w) {
    const int gwarp = (blockIdx.x * blockDim.x + threadIdx.x) >> 5;
    const int lane  = threadIdx.x & 31;
    if (gwarp >= NROWS + CROWS) return;

    const bool isx = gwarp < NROWS;
    const int r = isx ? gwarp : gwarp - NROWS;
    const float* base = isx ? (x + (size_t)r * DDIM) : (w + (size_t)r * DDIM);

    float4 v = reinterpret_cast<const float4*>(base)[lane];
    float f[4] = {v.x, v.y, v.z, v.w};

    float s = f[0]*f[0] + f[1]*f[1] + f[2]*f[2] + f[3]*f[3];
    #pragma unroll
    for (int o = 16; o > 0; o >>= 1)
        s += __shfl_xor_sync(0xffffffffu, s, o);

    uint32_t hb[4];
    #pragma unroll
    for (int i = 0; i < 4; i++)
        hb[i] = (uint32_t)__bfloat16_as_ushort(__float2bfloat16_rn(f[i]));
    uint2 H;
    H.x = hb[0] | (hb[1] << 16); H.y = hb[2] | (hb[3] << 16);

    __nv_bfloat16* dst = isx ? (g_xb + (size_t)r * DDIM) : (g_wb + (size_t)r * DDIM);
    reinterpret_cast<uint2*>(dst)[lane] = H;

    if (lane == 0) {
        if (isx) g_xsq[r] = s; else g_wsq[r] = s;
    }
}

// ---------------------------------------------------------------------------
// Kernel 2: bf16 GEMM (mma.sync m16n8k16) + fused distance epilogue with
// smem-staged, fully coalesced 128B output stores.
// CTA 128x128, K=128 resident, 8 warps: warp_m in {0,1} x warp_n in {0..3},
// warp tile 64x32. 2 CTAs/SM.
// ---------------------------------------------------------------------------
__global__ __launch_bounds__(256, 2)
void mma_dist_kernel(float* __restrict__ out) {
    extern __shared__ char sdyn[];
    const uint32_t Ab = smem_u32(sdyn);
    const uint32_t Bb = Ab + 32768;

    const int tid    = threadIdx.x;
    const int lane   = tid & 31;
    const int wid    = tid >> 5;
    const int warp_m = wid & 1;          // 2 x 64 rows
    const int warp_n = wid >> 1;         // 4 x 32 cols
    const int bn     = blockIdx.x * BN;  // prototype tiles (8)
    const int bm     = blockIdx.y * BM;  // x tiles (1024)

    // ---- Load whole A and B tiles (2048 16B units each; 8 per thread) ----
    {
        const __nv_bfloat16* srcA = g_xb + (size_t)bm * DDIM;
        const __nv_bfloat16* srcB = g_wb + (size_t)bn * DDIM;
        #pragma unroll
        for (int i = 0; i < 8; i++) {
            const int c = tid + i * 256;
            const int r = c >> 4, u = c & 15;
            const uint32_t off = tile_off(r, u);
            cp_async16(Ab + off, srcA + r * DDIM + u * 8);
            cp_async16(Bb + off, srcB + r * DDIM + u * 8);
        }
        CP_COMMIT();
    }

    float acc[4][4][4];
    #pragma unroll
    for (int mi = 0; mi < 4; mi++)
        #pragma unroll
        for (int ni = 0; ni < 4; ni++)
            #pragma unroll
            for (int q = 0; q < 4; q++)
                acc[mi][ni][q] = 0.0f;

    // ldmatrix lane-address components
    const int a_row = warp_m * 64 + (lane & 15);                      // + mi*16
    const int a_u0  = lane >> 4;                                      // + ks*2
    const int b_row = warp_n * 32 + (lane & 7) + ((lane >> 4) << 3);  // + nj*16
    const int b_u0  = (lane >> 3) & 1;                                // + ks*2

    CP_WAIT0();
    __syncthreads();

    #pragma unroll
    for (int ks = 0; ks < 8; ks++) {
        uint32_t a[4][4], b[4][2];
        #pragma unroll
        for (int mi = 0; mi < 4; mi++)
            ldsm_x4(a[mi][0], a[mi][1], a[mi][2], a[mi][3],
                    Ab + tile_off(a_row + mi * 16, a_u0 + ks * 2));
        #pragma unroll
        for (int nj = 0; nj < 2; nj++)   // x4 -> fragments for ni=2*nj, 2*nj+1
            ldsm_x4(b[2*nj][0], b[2*nj][1], b[2*nj+1][0], b[2*nj+1][1],
                    Bb + tile_off(b_row + nj * 16, b_u0 + ks * 2));
        #pragma unroll
        for (int mi = 0; mi < 4; mi++)
            #pragma unroll
            for (int ni = 0; ni < 4; ni++)
                mma16816(acc[mi][ni], a[mi], b[ni]);
    }

    // ---- Epilogue phase 1: compute distances, stage into warp-private smem.
    // Tiles are dead after the barrier; warp w owns bytes [w*8192, w*8192+8192).
    __syncthreads();
    const uint32_t Sb = Ab + (uint32_t)wid * 8192;   // 64 rows x 128B

    const int er = lane >> 2;          // 0..7  (== staged row & 7 for both rows)
    const int ec = (lane & 3) * 2;
    float ws[4][2];
    #pragma unroll
    for (int ni = 0; ni < 4; ni++) {
        const int n = bn + warp_n * 32 + ni * 8 + ec;
        ws[ni][0] = g_wsq[n];
        ws[ni][1] = g_wsq[n + 1];
    }

    char* sp = sdyn + (size_t)wid * 8192;
    #pragma unroll
    for (int mi = 0; mi < 4; mi++) {
        const int wr0 = mi * 16 + er;          // warp-local rows
        const float xs0 = g_xsq[bm + warp_m * 64 + wr0];
        const float xs1 = g_xsq[bm + warp_m * 64 + wr0 + 8];
        #pragma unroll
        for (int ni = 0; ni < 4; ni++) {
            const int u = ni * 4 + (lane & 3);
            const uint32_t up = (uint32_t)(((u + 2 * er) & 15) << 3);
            float2 o0, o1;
            o0.x = fmaf(-2.0f, acc[mi][ni][0], xs0 + ws[ni][0]);
            o0.y = fmaf(-2.0f, acc[mi][ni][1], xs0 + ws[ni][1]);
            o1.x = fmaf(-2.0f, acc[mi][ni][2], xs1 + ws[ni][0]);
            o1.y = fmaf(-2.0f, acc[mi][ni][3], xs1 + ws[ni][1]);
            *reinterpret_cast<float2*>(sp + wr0 * 128 + up)        = o0;
            *reinterpret_cast<float2*>(sp + (wr0 + 8) * 128 + up)  = o1;
        }
    }
    __syncwarp();

    // ---- Epilogue phase 2: read back and store fully coalesced 128B lines.
    // iteration j: rows 4j..4j+3 of the warp tile; lane -> (row, 16B chunk).
    const int rr = lane >> 3;          // 0..3
    const int kk = lane & 7;           // 0..7 -> cols kk*4..kk*4+3
    float* obase = out + (size_t)(bm + warp_m * 64) * CROWS + bn + warp_n * 32 + kk * 4;
    #pragma unroll
    for (int j = 0; j < 16; j++) {
        const int wr = 4 * j + rr;
        float4 v = *reinterpret_cast<const float4*>(sp + stage_off(wr, kk * 2));
        stcs_f4(obase + (size_t)wr * CROWS, v);
    }
    (void)Sb;
}

// ---------------------------------------------------------------------------
extern "C" void kernel_launch(void* const* d_in, const int* in_sizes, int n_in,
                              void* d_out, int out_size) {
    const float* x = (const float*)d_in[0];   // [N, D]
    const float* w = (const float*)d_in[1];   // [C, D]
    float* out = (float*)d_out;               // [N, C]

    static bool attr_set = false;
    if (!attr_set) {
        cudaFuncSetAttribute(mma_dist_kernel,
                             cudaFuncAttributeMaxDynamicSharedMemorySize, SMEM_NEED);
        attr_set = true;
    }

    // 1) bf16 conversion + norms (warp per row)
    const int total_rows = NROWS + CROWS;
    const int blocks = (total_rows * 32 + 255) / 256;
    convert_kernel<<<blocks, 256>>>(x, w);

    // 2) tensor-core (mma.sync) distance GEMM with coalesced epilogue
    dim3 grid(CROWS / BN, NROWS / BM);  // (8, 1024)
    mma_dist_kernel<<<grid, 256, SMEM_NEED>>>(out);
}

// round 13
// speedup vs baseline: 1.0871x; 1.0871x over previous
#include <cuda_runtime.h>
#include <cuda_bf16.h>
#include <cstdint>

// Problem constants (fixed: N=131072, C=1024, D=128)
#define NROWS 131072
#define CROWS 1024
#define DDIM  128

#define BM 128
#define BN 128
#define NKS 8                 // k-steps of 16
#define NBLK16_X (NROWS / 16) // 8192 16-row A blocks
#define NBLK16_W (CROWS / 16) // 64   16-col B blocks

// ---------------------------------------------------------------------------
// Device scratch (no cudaMalloc allowed)
// Fragment layouts: [block16][kstep][lane] -> uint4 (16B per lane)
//   A uint4 = {a0,a1,a2,a3} of mma.m16n8k16 A fragment
//   B uint4 = {b0(n8 lo),b1(n8 lo),b0(n8 hi),b1(n8 hi)} covering 16 cols
// ---------------------------------------------------------------------------
__device__ float g_xsq[NROWS];
__device__ float g_wsq[CROWS];
__device__ uint4 g_xaf[(size_t)NBLK16_X * NKS * 32];  // 33.5 MB
__device__ uint4 g_wbf[(size_t)NBLK16_W * NKS * 32];  // 256 KB

// ---------------------------------------------------------------------------
// PTX helpers — base-target-safe only (NO tcgen05: harness targets plain sm_103)
// ---------------------------------------------------------------------------
__device__ __forceinline__ void mma16816(float* c, const uint32_t* a,
                                         const uint32_t* b) {
    asm volatile(
        "mma.sync.aligned.m16n8k16.row.col.f32.bf16.bf16.f32 "
        "{%0,%1,%2,%3}, {%4,%5,%6,%7}, {%8,%9}, {%0,%1,%2,%3};"
        : "+f"(c[0]), "+f"(c[1]), "+f"(c[2]), "+f"(c[3])
        : "r"(a[0]), "r"(a[1]), "r"(a[2]), "r"(a[3]), "r"(b[0]), "r"(b[1]));
}

__device__ __forceinline__ void stcs_f2(float* p, float2 v) {
    asm volatile("st.global.cs.v2.f32 [%0], {%1,%2};" :: "l"(p), "f"(v.x), "f"(v.y)
                 : "memory");
}

__device__ __forceinline__ uint32_t pack_bf16(float a, float b) {
    uint32_t lo = (uint32_t)__bfloat16_as_ushort(__float2bfloat16_rn(a));
    uint32_t hi = (uint32_t)__bfloat16_as_ushort(__float2bfloat16_rn(b));
    return lo | (hi << 16);
}

// ---------------------------------------------------------------------------
// Kernel 1: fp32 -> bf16 fragment-layout conversion + exact fp32 row norms.
// One 128-thread block per 16-row block (X: 8192 blocks, W: 64 blocks).
// Phase 1: coalesced load, per-row norms (8 threads/row), bf16 -> smem.
// Phase 2: gather mma fragments from smem, coalesced STG.128 to g_xaf/g_wbf.
// ---------------------------------------------------------------------------
#define CVT_PITCH 136   // bf16 elems per smem row (272B, bank-conflict-free)

__global__ __launch_bounds__(128)
void convert_kernel(const float* __restrict__ x, const float* __restrict__ w) {
    const int blk = blockIdx.x;
    const bool isx = blk < NBLK16_X;
    const int b16 = isx ? blk : blk - NBLK16_X;
    const float* src = (isx ? x : w) + (size_t)b16 * 16 * DDIM;

    __shared__ __nv_bfloat16 sb[16 * CVT_PITCH];

    const int t = threadIdx.x;         // 0..127
    const int r = t >> 3;              // row 0..15
    const int j = t & 7;               // 16-float chunk within row

    // ---- Phase 1: load, norm, bf16 to smem ----
    float4 v[4];
    const float4* s4 = reinterpret_cast<const float4*>(src + r * DDIM + j * 16);
    #pragma unroll
    for (int i = 0; i < 4; i++) v[i] = s4[i];

    float s = 0.0f;
    #pragma unroll
    for (int i = 0; i < 4; i++)
        s += v[i].x*v[i].x + v[i].y*v[i].y + v[i].z*v[i].z + v[i].w*v[i].w;
    #pragma unroll
    for (int o = 4; o > 0; o >>= 1)
        s += __shfl_xor_sync(0xffffffffu, s, o);
    if (j == 0) {
        if (isx) g_xsq[b16 * 16 + r] = s;
        else     g_wsq[b16 * 16 + r] = s;
    }

    {
        uint32_t* d = reinterpret_cast<uint32_t*>(sb + r * CVT_PITCH + j * 16);
        #pragma unroll
        for (int i = 0; i < 4; i++) {
            d[i * 2 + 0] = pack_bf16(v[i].x, v[i].y);
            d[i * 2 + 1] = pack_bf16(v[i].z, v[i].w);
        }
    }
    __syncthreads();

    // ---- Phase 2: fragment gather + coalesced store ----
    const int wv   = t >> 5;           // warp 0..3 -> ksteps {2wv, 2wv+1}
    const int lane = t & 31;
    const int gid  = lane >> 2;        // 0..7
    const int tig  = lane & 3;         // 0..3

    #pragma unroll
    for (int kk = 0; kk < 2; kk++) {
        const int ks = wv * 2 + kk;
        const int kc = ks * 16 + tig * 2;
        uint4 o;
        if (isx) {
            // A frag: a0=(gid,kc) a1=(gid+8,kc) a2=(gid,kc+8) a3=(gid+8,kc+8)
            o.x = pack_bf16(__bfloat162float(sb[gid * CVT_PITCH + kc]),
                            __bfloat162float(sb[gid * CVT_PITCH + kc + 1]));
            o.y = pack_bf16(__bfloat162float(sb[(gid + 8) * CVT_PITCH + kc]),
                            __bfloat162float(sb[(gid + 8) * CVT_PITCH + kc + 1]));
            o.z = pack_bf16(__bfloat162float(sb[gid * CVT_PITCH + kc + 8]),
                            __bfloat162float(sb[gid * CVT_PITCH + kc + 9]));
            o.w = pack_bf16(__bfloat162float(sb[(gid + 8) * CVT_PITCH + kc + 8]),
                            __bfloat162float(sb[(gid + 8) * CVT_PITCH + kc + 9]));
            g_xaf[((size_t)b16 * NKS + ks) * 32 + lane] = o;
        } else {
            // B frag (cols = prototype rows): n8-lo: n=gid, n8-hi: n=gid+8
            // b0 = w[n][kc],w[n][kc+1]; b1 = w[n][kc+8],w[n][kc+9]
            o.x = pack_bf16(__bfloat162float(sb[gid * CVT_PITCH + kc]),
                            __bfloat162float(sb[gid * CVT_PITCH + kc + 1]));
            o.y = pack_bf16(__bfloat162float(sb[gid * CVT_PITCH + kc + 8]),
                            __bfloat162float(sb[gid * CVT_PITCH + kc + 9]));
            o.z = pack_bf16(__bfloat162float(sb[(gid + 8) * CVT_PITCH + kc]),
                            __bfloat162float(sb[(gid + 8) * CVT_PITCH + kc + 1]));
            o.w = pack_bf16(__bfloat162float(sb[(gid + 8) * CVT_PITCH + kc + 8]),
                            __bfloat162float(sb[(gid + 8) * CVT_PITCH + kc + 9]));
            g_wbf[((size_t)b16 * NKS + ks) * 32 + lane] = o;
        }
    }
}

// ---------------------------------------------------------------------------
// Kernel 2: fragment-direct bf16 GEMM + fused distance epilogue.
// ZERO smem, ZERO barriers: each warp streams LDG.128 fragments -> HMMA -> STG.
// CTA 128x128 (logical), 8 warps: warp_m in {0,1} (64 rows) x warp_n in {0..3}
// (32 cols). Within-CTA fragment redundancy is absorbed by L1.
// ---------------------------------------------------------------------------
__global__ __launch_bounds__(256, 2)
void mma_dist_kernel(float* __restrict__ out) {
    const int tid    = threadIdx.x;
    const int lane   = tid & 31;
    const int wid    = tid >> 5;
    const int warp_m = wid & 1;          // 2 x 64 rows
    const int warp_n = wid >> 1;         // 4 x 32 cols
    const int bn     = blockIdx.x * BN;  // prototype tiles (8)
    const int bm     = blockIdx.y * BM;  // x tiles (1024)

    // fragment base pointers (uint4 granularity)
    const uint4* pA = g_xaf + ((size_t)(bm / 16 + warp_m * 4) * NKS) * 32 + lane;
    const uint4* pB = g_wbf + ((size_t)(bn / 16 + warp_n * 2) * NKS) * 32 + lane;
    // strides: +256 uint4 per 16-row block, +32 per kstep

    float acc[4][4][4];
    #pragma unroll
    for (int mi = 0; mi < 4; mi++)
        #pragma unroll
        for (int ni = 0; ni < 4; ni++)
            #pragma unroll
            for (int q = 0; q < 4; q++)
                acc[mi][ni][q] = 0.0f;

    #pragma unroll
    for (int ks = 0; ks < NKS; ks++) {
        uint4 af[4], bf[2];
        #pragma unroll
        for (int mi = 0; mi < 4; mi++)
            af[mi] = pA[ks * 32 + mi * (NKS * 32)];
        #pragma unroll
        for (int nj = 0; nj < 2; nj++)
            bf[nj] = pB[ks * 32 + nj * (NKS * 32)];

        uint32_t a[4][4], b[4][2];
        #pragma unroll
        for (int mi = 0; mi < 4; mi++) {
            a[mi][0] = af[mi].x; a[mi][1] = af[mi].y;
            a[mi][2] = af[mi].z; a[mi][3] = af[mi].w;
        }
        #pragma unroll
        for (int nj = 0; nj < 2; nj++) {
            b[2*nj][0]   = bf[nj].x; b[2*nj][1]   = bf[nj].y;
            b[2*nj+1][0] = bf[nj].z; b[2*nj+1][1] = bf[nj].w;
        }
        #pragma unroll
        for (int mi = 0; mi < 4; mi++)
            #pragma unroll
            for (int ni = 0; ni < 4; ni++)
                mma16816(acc[mi][ni], a[mi], b[ni]);
    }

    // ---- Epilogue: dist = xsq + wsq - 2*acc (direct streaming stores) ----
    const int er = lane >> 2;
    const int ec = (lane & 3) * 2;
    float ws[4][2];
    #pragma unroll
    for (int ni = 0; ni < 4; ni++) {
        const int n = bn + warp_n * 32 + ni * 8 + ec;
        ws[ni][0] = g_wsq[n];
        ws[ni][1] = g_wsq[n + 1];
    }
    #pragma unroll
    for (int mi = 0; mi < 4; mi++) {
        const int r0 = bm + warp_m * 64 + mi * 16 + er;
        const int r1 = r0 + 8;
        const float xs0 = g_xsq[r0];
        const float xs1 = g_xsq[r1];
        float* row0 = out + (size_t)r0 * CROWS + bn + warp_n * 32 + ec;
        float* row1 = out + (size_t)r1 * CROWS + bn + warp_n * 32 + ec;
        #pragma unroll
        for (int ni = 0; ni < 4; ni++) {
            float2 o0, o1;
            o0.x = fmaf(-2.0f, acc[mi][ni][0], xs0 + ws[ni][0]);
            o0.y = fmaf(-2.0f, acc[mi][ni][1], xs0 + ws[ni][1]);
            o1.x = fmaf(-2.0f, acc[mi][ni][2], xs1 + ws[ni][0]);
            o1.y = fmaf(-2.0f, acc[mi][ni][3], xs1 + ws[ni][1]);
            stcs_f2(row0 + ni * 8, o0);
            stcs_f2(row1 + ni * 8, o1);
        }
    }
}

// ---------------------------------------------------------------------------
extern "C" void kernel_launch(void* const* d_in, const int* in_sizes, int n_in,
                              void* d_out, int out_size) {
    const float* x = (const float*)d_in[0];   // [N, D]
    const float* w = (const float*)d_in[1];   // [C, D]
    float* out = (float*)d_out;               // [N, C]

    // 1) fragment-layout bf16 conversion + norms
    convert_kernel<<<NBLK16_X + NBLK16_W, 128>>>(x, w);

    // 2) fragment-direct tensor-core distance GEMM (no smem, no barriers)
    dim3 grid(CROWS / BN, NROWS / BM);  // (8, 1024)
    mma_dist_kernel<<<grid, 256>>>(out);
}